// round 1
// baseline (speedup 1.0000x reference)
#include <cuda_runtime.h>
#include <math.h>

// ---------------------------------------------------------------------------
// WindowAttentionV2: b=4096 windows, n=64 tokens, C=384, H=12 heads, d=32
// Pipeline: cpb_tab -> cpb_gather -> qkv GEMM -> fused attention -> proj GEMM
// ---------------------------------------------------------------------------

#define BWIN   4096
#define NTOK   64
#define CDIM   384
#define HEADS  12
#define HDIM   32
#define NWIN   1024
#define M1     (BWIN * NTOK)          // 262144 rows
#define QKV_N  (3 * CDIM)             // 1152
#define QKV_STRIDE (BWIN * HEADS * NTOK * HDIM)   // 100663296 per tensor

// Scratch (device globals; no allocations allowed)
__device__ float g_qkv[3ll * QKV_STRIDE];          // [3][b][h][n][d]
__device__ float g_att[(long long)M1 * CDIM];      // [b*n][h*32+d]
__device__ float g_tab[4096 * HEADS];              // MLP table
__device__ float g_bias[HEADS * NTOK * NTOK];      // 16*sigmoid(gathered)

// ---------------------------------------------------------------------------
// Kernel 1a: continuous position bias MLP table: tab[i][h]
// ---------------------------------------------------------------------------
__global__ void cpb_tab_kernel(const float* __restrict__ table,
                               const float* __restrict__ w1,
                               const float* __restrict__ b1,
                               const float* __restrict__ w2)
{
    int i = blockIdx.x * blockDim.x + threadIdx.x;
    if (i >= 4096) return;
    float t0 = table[i * 2 + 0];
    float t1 = table[i * 2 + 1];
    float out[HEADS];
    #pragma unroll
    for (int h = 0; h < HEADS; h++) out[h] = 0.f;
    for (int j = 0; j < 512; j++) {
        float hd = fmaxf(fmaf(t0, w1[j], fmaf(t1, w1[512 + j], b1[j])), 0.f);
        #pragma unroll
        for (int h = 0; h < HEADS; h++) out[h] += hd * w2[j * HEADS + h];
    }
    #pragma unroll
    for (int h = 0; h < HEADS; h++) g_tab[i * HEADS + h] = out[h];
}

// ---------------------------------------------------------------------------
// Kernel 1b: gather + 16*sigmoid -> g_bias[h][q][k]
// ---------------------------------------------------------------------------
__global__ void cpb_gather_kernel(const int* __restrict__ index)
{
    int e = blockIdx.x * blockDim.x + threadIdx.x;
    if (e >= HEADS * 4096) return;
    int h = e / 4096;
    int qk = e % 4096;
    float v = g_tab[index[qk] * HEADS + h];
    g_bias[e] = 16.f / (1.f + expf(-v));
}

// ---------------------------------------------------------------------------
// SGEMM 128x128x8, 8x8 per-thread tiles, 256 threads.
//   EPI==0: qkv gemm (A = Ain = x), bias add, scatter to g_qkv [3][b][h][n][d]
//   EPI==1: proj gemm (A = g_att), bias add, write dense to Cout
// ---------------------------------------------------------------------------
template <int EPI>
__global__ __launch_bounds__(256)
void sgemm128(const float* __restrict__ Ain,
              const float* __restrict__ Bw,
              const float* __restrict__ bias,
              float* __restrict__ Cout,
              int M, int N, int K)
{
    const int BM = 128, BN = 128, BK = 8, TM = 8, TN = 8;
    __shared__ float As[BK][BM];
    __shared__ float Bs[BK][BN];

    const float* A = (EPI == 1) ? (const float*)g_att : Ain;

    int tid = threadIdx.x;
    int crow = blockIdx.y * BM;
    int ccol = blockIdx.x * BN;

    int aRow = tid >> 1;             // 0..127
    int aCol = (tid & 1) * 4;        // 0 or 4
    int bRow = tid >> 5;             // 0..7
    int bCol = (tid & 31) * 4;       // 0..124

    const float* Aptr = A + (long long)(crow + aRow) * K + aCol;
    const float* Bptr = Bw + (long long)bRow * N + ccol + bCol;

    int tr = tid >> 4;               // 0..15
    int tc = tid & 15;               // 0..15

    float acc[TM][TN];
    #pragma unroll
    for (int i = 0; i < TM; i++)
        #pragma unroll
        for (int j = 0; j < TN; j++) acc[i][j] = 0.f;

    float regM[TM], regN[TN];

    for (int k0 = 0; k0 < K; k0 += BK) {
        float4 av = *(const float4*)(Aptr + k0);
        As[aCol + 0][aRow] = av.x;
        As[aCol + 1][aRow] = av.y;
        As[aCol + 2][aRow] = av.z;
        As[aCol + 3][aRow] = av.w;
        *(float4*)(&Bs[bRow][bCol]) = *(const float4*)(Bptr + (long long)k0 * N);
        __syncthreads();
        #pragma unroll
        for (int k = 0; k < BK; k++) {
            #pragma unroll
            for (int i = 0; i < TM; i++) regM[i] = As[k][tr * TM + i];
            #pragma unroll
            for (int j = 0; j < TN; j++) regN[j] = Bs[k][tc * TN + j];
            #pragma unroll
            for (int i = 0; i < TM; i++)
                #pragma unroll
                for (int j = 0; j < TN; j++) acc[i][j] += regM[i] * regN[j];
        }
        __syncthreads();
    }

    if (EPI == 0) {
        // scatter into [3][b][h][n][d]
        #pragma unroll
        for (int i = 0; i < TM; i++) {
            int m = crow + tr * TM + i;
            int b = m >> 6;
            int n = m & 63;
            #pragma unroll
            for (int j = 0; j < TN; j++) {
                int col = ccol + tc * TN + j;
                float v = acc[i][j] + bias[col];
                int three = col / CDIM;
                int rem   = col - three * CDIM;
                int head  = rem >> 5;
                int dd    = rem & 31;
                long long off = (long long)three * QKV_STRIDE +
                                (((long long)(b * HEADS + head)) * NTOK + n) * HDIM + dd;
                g_qkv[off] = v;
            }
        }
    } else {
        #pragma unroll
        for (int i = 0; i < TM; i++) {
            int m = crow + tr * TM + i;
            #pragma unroll
            for (int j = 0; j < TN; j++) {
                int col = ccol + tc * TN + j;
                Cout[(long long)m * N + col] = acc[i][j] + bias[col];
            }
        }
    }
}

// ---------------------------------------------------------------------------
// Fused attention: one block per (b, h). 256 threads.
//   load q/k/v [64][32] -> l2norm q,k -> scores + bias + mask -> softmax -> @v
// ---------------------------------------------------------------------------
__global__ __launch_bounds__(256)
void attn_kernel(const float* __restrict__ mask,
                 const float* __restrict__ logit_scale)
{
    int bh = blockIdx.x;
    int b = bh / HEADS;
    int h = bh - b * HEADS;

    __shared__ float qs[64 * 33];
    __shared__ float ks[64 * 33];
    __shared__ float vs[64 * 33];
    __shared__ float sc[64 * 65];

    int tid  = threadIdx.x;
    int warp = tid >> 5;
    int lane = tid & 31;

    const float* qg = g_qkv + (long long)bh * (NTOK * HDIM);
    const float* kg = qg + QKV_STRIDE;
    const float* vg = kg + QKV_STRIDE;

    // load 2048 floats each as float4 with padded-row smem
    for (int e = tid; e < 512; e += 256) {
        int r = e >> 3;
        int c = (e & 7) * 4;
        float4 q4 = ((const float4*)qg)[e];
        float4 k4 = ((const float4*)kg)[e];
        float4 v4 = ((const float4*)vg)[e];
        float* dq = &qs[r * 33 + c];
        float* dk = &ks[r * 33 + c];
        float* dv = &vs[r * 33 + c];
        dq[0] = q4.x; dq[1] = q4.y; dq[2] = q4.z; dq[3] = q4.w;
        dk[0] = k4.x; dk[1] = k4.y; dk[2] = k4.z; dk[3] = k4.w;
        dv[0] = v4.x; dv[1] = v4.y; dv[2] = v4.z; dv[3] = v4.w;
    }
    __syncthreads();

    // l2 normalize q and k rows (128 rows, 16 per warp, lane = column)
    #pragma unroll
    for (int i = 0; i < 16; i++) {
        int r = warp * 16 + i;
        float* buf = (r < 64) ? &qs[r * 33] : &ks[(r - 64) * 33];
        float v = buf[lane];
        float ss = v * v;
        #pragma unroll
        for (int o = 16; o; o >>= 1) ss += __shfl_xor_sync(~0u, ss, o);
        buf[lane] = v / fmaxf(sqrtf(ss), 1e-12f);
    }
    __syncthreads();

    float scale = expf(fminf(logit_scale[h], 4.60517018598809f)); // ln(100)
    int w = b & (NWIN - 1);
    const float* mrow = mask + (long long)w * 4096;
    const float* brow = g_bias + h * 4096;

    // scores: 4096 elems / 256 threads; qi constant per warp, kj = consecutive
    for (int e = tid; e < 4096; e += 256) {
        int qi = e >> 6;
        int kj = e & 63;
        float acc = 0.f;
        #pragma unroll
        for (int l = 0; l < 32; l++) acc += qs[qi * 33 + l] * ks[kj * 33 + l];
        sc[qi * 65 + kj] = fmaf(acc, scale, brow[e] + mrow[e]);
    }
    __syncthreads();

    // softmax: each warp handles 8 rows; lane covers 2 of 64 columns
    #pragma unroll
    for (int i = 0; i < 8; i++) {
        int qi = warp * 8 + i;
        float a = sc[qi * 65 + lane];
        float c = sc[qi * 65 + 32 + lane];
        float mx = fmaxf(a, c);
        #pragma unroll
        for (int o = 16; o; o >>= 1) mx = fmaxf(mx, __shfl_xor_sync(~0u, mx, o));
        a = __expf(a - mx);
        c = __expf(c - mx);
        float sm = a + c;
        #pragma unroll
        for (int o = 16; o; o >>= 1) sm += __shfl_xor_sync(~0u, sm, o);
        float inv = 1.f / sm;
        sc[qi * 65 + lane]      = a * inv;
        sc[qi * 65 + 32 + lane] = c * inv;
    }
    __syncthreads();

    // out = attn @ v : 2048 outputs / 256 threads; dd consecutive per warp
    for (int e = tid; e < 2048; e += 256) {
        int qi = e >> 5;
        int dd = e & 31;
        float acc = 0.f;
        #pragma unroll
        for (int kj = 0; kj < 64; kj++) acc += sc[qi * 65 + kj] * vs[kj * 33 + dd];
        g_att[((long long)b * NTOK + qi) * CDIM + h * HDIM + dd] = acc;
    }
}

// ---------------------------------------------------------------------------
extern "C" void kernel_launch(void* const* d_in, const int* in_sizes, int n_in,
                              void* d_out, int out_size)
{
    const float* x           = (const float*)d_in[0];
    const float* mask        = (const float*)d_in[1];
    const float* qkv_w       = (const float*)d_in[2];
    const float* qkv_b       = (const float*)d_in[3];
    const float* proj_w      = (const float*)d_in[4];
    const float* proj_b      = (const float*)d_in[5];
    const float* logit_scale = (const float*)d_in[6];
    const float* cpb_w1      = (const float*)d_in[7];
    const float* cpb_b1      = (const float*)d_in[8];
    const float* cpb_w2      = (const float*)d_in[9];
    const float* rel_table   = (const float*)d_in[10];
    const int*   rel_index   = (const int*)d_in[11];
    float* out = (float*)d_out;

    // 1. continuous position bias
    cpb_tab_kernel<<<16, 256>>>(rel_table, cpb_w1, cpb_b1, cpb_w2);
    cpb_gather_kernel<<<192, 256>>>(rel_index);

    // 2. qkv gemm: [262144,384] x [384,1152]
    {
        dim3 grid(QKV_N / 128, M1 / 128);
        sgemm128<0><<<grid, 256>>>(x, qkv_w, qkv_b, nullptr, M1, QKV_N, CDIM);
    }

    // 3. fused window attention
    attn_kernel<<<BWIN * HEADS, 256>>>(mask, logit_scale);

    // 4. proj gemm: [262144,384] x [384,384]
    {
        dim3 grid(CDIM / 128, M1 / 128);
        sgemm128<1><<<grid, 256>>>(nullptr, proj_w, proj_b, out, M1, CDIM, CDIM);
    }
}

// round 3
// speedup vs baseline: 1.7523x; 1.7523x over previous
#include <cuda_runtime.h>
#include <cstdint>
#include <mma.h>
#include <math.h>

using namespace nvcuda;

// ---------------------------------------------------------------------------
// WindowAttentionV2: b=4096 windows, n=64 tokens, C=384, H=12 heads, d=32
// cpb_tab -> cpb_gather -> qkv GEMM (tf32 wmma) -> fused attention -> proj GEMM
// ---------------------------------------------------------------------------

#define BWIN   4096
#define NTOK   64
#define CDIM   384
#define HEADS  12
#define HDIM   32
#define NWIN   1024
#define M1     (BWIN * NTOK)          // 262144 rows
#define QKV_N  (3 * CDIM)             // 1152
#define QKV_STRIDE (BWIN * HEADS * NTOK * HDIM)   // per q/k/v tensor

// Scratch (device globals; no allocations allowed)
__device__ float g_qkv[3ll * QKV_STRIDE];          // [3][b][h][n][d]
__device__ float g_att[(long long)M1 * CDIM];      // [b*n][h*32+d]
__device__ float g_tab[4096 * HEADS];              // MLP table
__device__ float g_bias[HEADS * NTOK * NTOK];      // 16*sigmoid(gathered)

// ---------------------------------------------------------------------------
__global__ void cpb_tab_kernel(const float* __restrict__ table,
                               const float* __restrict__ w1,
                               const float* __restrict__ b1,
                               const float* __restrict__ w2)
{
    int i = blockIdx.x * blockDim.x + threadIdx.x;
    if (i >= 4096) return;
    float t0 = table[i * 2 + 0];
    float t1 = table[i * 2 + 1];
    float out[HEADS];
    #pragma unroll
    for (int h = 0; h < HEADS; h++) out[h] = 0.f;
    for (int j = 0; j < 512; j++) {
        float hd = fmaxf(fmaf(t0, w1[j], fmaf(t1, w1[512 + j], b1[j])), 0.f);
        #pragma unroll
        for (int h = 0; h < HEADS; h++) out[h] += hd * w2[j * HEADS + h];
    }
    #pragma unroll
    for (int h = 0; h < HEADS; h++) g_tab[i * HEADS + h] = out[h];
}

__global__ void cpb_gather_kernel(const int* __restrict__ index)
{
    int e = blockIdx.x * blockDim.x + threadIdx.x;
    if (e >= HEADS * 4096) return;
    int h = e / 4096;
    int qk = e % 4096;
    float v = g_tab[index[qk] * HEADS + h];
    g_bias[e] = 16.f / (1.f + expf(-v));
}

// ---------------------------------------------------------------------------
// tf32 tensor-core GEMM: 128x128 block tile, BK=16, cp.async double buffer.
// 8 warps: warp (wm 0..3, wn 0..1) owns 32(M) x 64(N) = 2x4 wmma 16x16 frags.
//   EPI==0: qkv gemm, +bias, scatter to g_qkv [3][b][h][n][d]
//   EPI==1: proj gemm, +bias, dense write to Cout
// ---------------------------------------------------------------------------
#define BM 128
#define BN 128
#define BKT 16
#define APAD 20    // As row stride (floats), mult of 4, rows 16B-aligned (80B)
#define BPAD 132   // Bs row stride (floats), mult of 4, rows 16B-aligned (528B)

__device__ __forceinline__ void cp16(void* s, const void* g)
{
    unsigned int sa = (unsigned int)__cvta_generic_to_shared(s);
    asm volatile("cp.async.cg.shared.global [%0], [%1], 16;\n" :: "r"(sa), "l"(g));
}

template <int EPI>
__global__ __launch_bounds__(256)
void tgemm(const float* __restrict__ Ain,
           const float* __restrict__ Bw,
           const float* __restrict__ bias,
           float* __restrict__ Cout,
           int N, int K)
{
    __shared__ float As[2][BM * APAD];
    __shared__ float Bs[2][BKT * BPAD];
    __shared__ float ep[8][256];

    const float* A = (EPI == 1) ? (const float*)g_att : Ain;

    int tid  = threadIdx.x;
    int lane = tid & 31;
    int warp = tid >> 5;
    int wm = warp >> 1;
    int wn = warp & 1;
    long long crow = (long long)blockIdx.y * BM;
    int ccol = blockIdx.x * BN;

    // per-thread load coords (2 float4 each for A and B per stage)
    int ar[2], ac[2], br[2], bc[2];
    #pragma unroll
    for (int s = 0; s < 2; s++) {
        int i = tid + s * 256;
        ar[s] = i >> 2;  ac[s] = (i & 3) * 4;
        br[s] = i >> 5;  bc[s] = (i & 31) * 4;
    }

    wmma::fragment<wmma::accumulator, 16, 16, 8, float> acc[2][4];
    #pragma unroll
    for (int i = 0; i < 2; i++)
        #pragma unroll
        for (int j = 0; j < 4; j++) wmma::fill_fragment(acc[i][j], 0.f);

    const int NK = K / BKT;

    // issue stage kt into buffer buf
    auto issue = [&](int buf, int kt) {
        int k0 = kt * BKT;
        #pragma unroll
        for (int s = 0; s < 2; s++) {
            cp16(&As[buf][ar[s] * APAD + ac[s]],
                 A + (crow + ar[s]) * K + k0 + ac[s]);
            cp16(&Bs[buf][br[s] * BPAD + bc[s]],
                 Bw + (long long)(k0 + br[s]) * N + ccol + bc[s]);
        }
        asm volatile("cp.async.commit_group;\n");
    };

    issue(0, 0);

    for (int kt = 0; kt < NK; kt++) {
        if (kt + 1 < NK) {
            issue((kt + 1) & 1, kt + 1);
            asm volatile("cp.async.wait_group 1;\n");
        } else {
            asm volatile("cp.async.wait_group 0;\n");
        }
        __syncthreads();

        int buf = kt & 1;
        #pragma unroll
        for (int kk = 0; kk < BKT; kk += 8) {
            wmma::fragment<wmma::matrix_a, 16, 16, 8, wmma::precision::tf32, wmma::row_major> af[2];
            wmma::fragment<wmma::matrix_b, 16, 16, 8, wmma::precision::tf32, wmma::row_major> bf[4];
            #pragma unroll
            for (int i = 0; i < 2; i++) {
                wmma::load_matrix_sync(af[i], &As[buf][(wm * 32 + i * 16) * APAD + kk], APAD);
                #pragma unroll
                for (int t = 0; t < af[i].num_elements; t++)
                    af[i].x[t] = wmma::__float_to_tf32(af[i].x[t]);
            }
            #pragma unroll
            for (int j = 0; j < 4; j++) {
                wmma::load_matrix_sync(bf[j], &Bs[buf][kk * BPAD + wn * 64 + j * 16], BPAD);
                #pragma unroll
                for (int t = 0; t < bf[j].num_elements; t++)
                    bf[j].x[t] = wmma::__float_to_tf32(bf[j].x[t]);
            }
            #pragma unroll
            for (int i = 0; i < 2; i++)
                #pragma unroll
                for (int j = 0; j < 4; j++)
                    wmma::mma_sync(acc[i][j], af[i], bf[j], acc[i][j]);
        }
        __syncthreads();
    }

    // epilogue: per-frag through warp-private smem patch
    #pragma unroll
    for (int i = 0; i < 2; i++) {
        #pragma unroll
        for (int j = 0; j < 4; j++) {
            wmma::store_matrix_sync(ep[warp], acc[i][j], 16, wmma::mem_row_major);
            __syncwarp();
            long long m0 = crow + wm * 32 + i * 16;
            int c0 = ccol + wn * 64 + j * 16;
            #pragma unroll
            for (int e = 0; e < 8; e++) {
                int idx = lane + e * 32;
                int r = idx >> 4;
                int c = idx & 15;
                float v = ep[warp][idx] + bias[c0 + c];
                if (EPI == 0) {
                    long long m = m0 + r;
                    int b = (int)(m >> 6);
                    int n = (int)(m & 63);
                    int col = c0 + c;
                    int three = col / CDIM;
                    int rem   = col - three * CDIM;
                    int head  = rem >> 5;
                    int dd    = rem & 31;
                    long long off = (long long)three * QKV_STRIDE +
                                    (((long long)(b * HEADS + head)) * NTOK + n) * HDIM + dd;
                    g_qkv[off] = v;
                } else {
                    Cout[(m0 + r) * N + c0 + c] = v;
                }
            }
            __syncwarp();
        }
    }
}

// ---------------------------------------------------------------------------
// Fused attention: one block per (b, h). 256 threads. (fp32)
// ---------------------------------------------------------------------------
__global__ __launch_bounds__(256)
void attn_kernel(const float* __restrict__ mask,
                 const float* __restrict__ logit_scale)
{
    int bh = blockIdx.x;
    int b = bh / HEADS;
    int h = bh - b * HEADS;

    __shared__ float qs[64 * 33];
    __shared__ float ks[64 * 33];
    __shared__ float vs[64 * 33];
    __shared__ float sc[64 * 65];

    int tid  = threadIdx.x;
    int warp = tid >> 5;
    int lane = tid & 31;

    const float* qg = g_qkv + (long long)bh * (NTOK * HDIM);
    const float* kg = qg + QKV_STRIDE;
    const float* vg = kg + QKV_STRIDE;

    for (int e = tid; e < 512; e += 256) {
        int r = e >> 3;
        int c = (e & 7) * 4;
        float4 q4 = ((const float4*)qg)[e];
        float4 k4 = ((const float4*)kg)[e];
        float4 v4 = ((const float4*)vg)[e];
        float* dq = &qs[r * 33 + c];
        float* dk = &ks[r * 33 + c];
        float* dv = &vs[r * 33 + c];
        dq[0] = q4.x; dq[1] = q4.y; dq[2] = q4.z; dq[3] = q4.w;
        dk[0] = k4.x; dk[1] = k4.y; dk[2] = k4.z; dk[3] = k4.w;
        dv[0] = v4.x; dv[1] = v4.y; dv[2] = v4.z; dv[3] = v4.w;
    }
    __syncthreads();

    #pragma unroll
    for (int i = 0; i < 16; i++) {
        int r = warp * 16 + i;
        float* buf = (r < 64) ? &qs[r * 33] : &ks[(r - 64) * 33];
        float v = buf[lane];
        float ss = v * v;
        #pragma unroll
        for (int o = 16; o; o >>= 1) ss += __shfl_xor_sync(~0u, ss, o);
        buf[lane] = v / fmaxf(sqrtf(ss), 1e-12f);
    }
    __syncthreads();

    float scale = expf(fminf(logit_scale[h], 4.60517018598809f)); // ln(100)
    int w = b & (NWIN - 1);
    const float* mrow = mask + (long long)w * 4096;
    const float* brow = g_bias + h * 4096;

    for (int e = tid; e < 4096; e += 256) {
        int qi = e >> 6;
        int kj = e & 63;
        float acc = 0.f;
        #pragma unroll
        for (int l = 0; l < 32; l++) acc += qs[qi * 33 + l] * ks[kj * 33 + l];
        sc[qi * 65 + kj] = fmaf(acc, scale, brow[e] + mrow[e]);
    }
    __syncthreads();

    #pragma unroll
    for (int i = 0; i < 8; i++) {
        int qi = warp * 8 + i;
        float a = sc[qi * 65 + lane];
        float c = sc[qi * 65 + 32 + lane];
        float mx = fmaxf(a, c);
        #pragma unroll
        for (int o = 16; o; o >>= 1) mx = fmaxf(mx, __shfl_xor_sync(~0u, mx, o));
        a = __expf(a - mx);
        c = __expf(c - mx);
        float sm = a + c;
        #pragma unroll
        for (int o = 16; o; o >>= 1) sm += __shfl_xor_sync(~0u, sm, o);
        float inv = 1.f / sm;
        sc[qi * 65 + lane]      = a * inv;
        sc[qi * 65 + 32 + lane] = c * inv;
    }
    __syncthreads();

    for (int e = tid; e < 2048; e += 256) {
        int qi = e >> 5;
        int dd = e & 31;
        float acc = 0.f;
        #pragma unroll
        for (int kj = 0; kj < 64; kj++) acc += sc[qi * 65 + kj] * vs[kj * 33 + dd];
        g_att[((long long)b * NTOK + qi) * CDIM + h * HDIM + dd] = acc;
    }
}

// ---------------------------------------------------------------------------
extern "C" void kernel_launch(void* const* d_in, const int* in_sizes, int n_in,
                              void* d_out, int out_size)
{
    const float* x           = (const float*)d_in[0];
    const float* mask        = (const float*)d_in[1];
    const float* qkv_w       = (const float*)d_in[2];
    const float* qkv_b       = (const float*)d_in[3];
    const float* proj_w      = (const float*)d_in[4];
    const float* proj_b      = (const float*)d_in[5];
    const float* logit_scale = (const float*)d_in[6];
    const float* cpb_w1      = (const float*)d_in[7];
    const float* cpb_b1      = (const float*)d_in[8];
    const float* cpb_w2      = (const float*)d_in[9];
    const float* rel_table   = (const float*)d_in[10];
    const int*   rel_index   = (const int*)d_in[11];
    float* out = (float*)d_out;

    cpb_tab_kernel<<<16, 256>>>(rel_table, cpb_w1, cpb_b1, cpb_w2);
    cpb_gather_kernel<<<192, 256>>>(rel_index);

    // qkv gemm: [262144,384] x [384,1152] (tf32 tensor cores)
    {
        dim3 grid(QKV_N / BN, M1 / BM);
        tgemm<0><<<grid, 256>>>(x, qkv_w, qkv_b, nullptr, QKV_N, CDIM);
    }

    attn_kernel<<<BWIN * HEADS, 256>>>(mask, logit_scale);

    // proj gemm: [262144,384] x [384,384] (tf32 tensor cores)
    {
        dim3 grid(CDIM / BN, M1 / BM);
        tgemm<1><<<grid, 256>>>(nullptr, proj_w, proj_b, out, CDIM, CDIM);
    }
}

// round 4
// speedup vs baseline: 1.9800x; 1.1300x over previous
#include <cuda_runtime.h>
#include <cstdint>
#include <mma.h>
#include <math.h>

using namespace nvcuda;

// ---------------------------------------------------------------------------
// WindowAttentionV2: b=4096 windows, n=64 tokens, C=384, H=12 heads, d=32
// ---------------------------------------------------------------------------

#define BWIN   4096
#define NTOK   64
#define CDIM   384
#define HEADS  12
#define HDIM   32
#define NWIN   1024
#define M1     (BWIN * NTOK)          // 262144 rows
#define QKV_N  (3 * CDIM)             // 1152
#define QKV_STRIDE (BWIN * HEADS * NTOK * HDIM)

// Scratch (device globals; no allocations allowed)
__device__ float g_qkv[3ll * QKV_STRIDE];          // [3][b][h][n][d] (no bias)
__device__ float g_att[(long long)M1 * CDIM];      // [b*n][h*32+d]
__device__ float g_tab[4096 * HEADS];
__device__ float g_bias[HEADS * NTOK * NTOK];

// ---------------------------------------------------------------------------
__global__ void cpb_tab_kernel(const float* __restrict__ table,
                               const float* __restrict__ w1,
                               const float* __restrict__ b1,
                               const float* __restrict__ w2)
{
    int i = blockIdx.x * blockDim.x + threadIdx.x;
    if (i >= 4096) return;
    float t0 = table[i * 2 + 0];
    float t1 = table[i * 2 + 1];
    float out[HEADS];
    #pragma unroll
    for (int h = 0; h < HEADS; h++) out[h] = 0.f;
    for (int j = 0; j < 512; j++) {
        float hd = fmaxf(fmaf(t0, w1[j], fmaf(t1, w1[512 + j], b1[j])), 0.f);
        #pragma unroll
        for (int h = 0; h < HEADS; h++) out[h] += hd * w2[j * HEADS + h];
    }
    #pragma unroll
    for (int h = 0; h < HEADS; h++) g_tab[i * HEADS + h] = out[h];
}

__global__ void cpb_gather_kernel(const int* __restrict__ index)
{
    int e = blockIdx.x * blockDim.x + threadIdx.x;
    if (e >= HEADS * 4096) return;
    int h = e / 4096;
    int qk = e % 4096;
    float v = g_tab[index[qk] * HEADS + h];
    g_bias[e] = 16.f / (1.f + expf(-v));
}

// ---------------------------------------------------------------------------
// tf32 GEMM: 128x128 tile, BK=16, 4-stage cp.async ring, 1 sync per K-step.
// 8 warps; warp (wm 0..3, wn 0..1) owns 32x64 = 2x4 wmma 16x16 frags.
//   EPI==0: qkv gemm, NO bias, dense frag store into g_qkv [3][b][h][n][d]
//   EPI==1: proj gemm, +bias via smem patch (reuses stage mem), dense write
// ---------------------------------------------------------------------------
#define BM 128
#define BN 128
#define BKT 16
#define APAD 20
#define BPAD 132
#define NSTAGE 4
#define AS_STAGE (BM * APAD)      // 2560 floats
#define BS_STAGE (BKT * BPAD)     // 2112 floats
#define GEMM_SMEM_BYTES (NSTAGE * (AS_STAGE + BS_STAGE) * 4)   // 74752

__device__ __forceinline__ void cp16(void* s, const void* g)
{
    unsigned int sa = (unsigned int)__cvta_generic_to_shared(s);
    asm volatile("cp.async.cg.shared.global [%0], [%1], 16;\n" :: "r"(sa), "l"(g));
}

template <int EPI>
__global__ __launch_bounds__(256)
void tgemm(const float* __restrict__ Ain,
           const float* __restrict__ Bw,
           const float* __restrict__ bias,
           float* __restrict__ Cout,
           int N, int K)
{
    extern __shared__ float dsm[];
    float* As = dsm;                       // NSTAGE * AS_STAGE
    float* Bs = dsm + NSTAGE * AS_STAGE;   // NSTAGE * BS_STAGE

    const float* A = (EPI == 1) ? (const float*)g_att : Ain;

    int tid  = threadIdx.x;
    int lane = tid & 31;
    int warp = tid >> 5;
    int wm = warp >> 1;
    int wn = warp & 1;
    long long crow = (long long)blockIdx.y * BM;
    int ccol = blockIdx.x * BN;

    int ar[2], ac[2], br[2], bc[2];
    #pragma unroll
    for (int s = 0; s < 2; s++) {
        int i = tid + s * 256;
        ar[s] = i >> 2;  ac[s] = (i & 3) * 4;
        br[s] = i >> 5;  bc[s] = (i & 31) * 4;
    }

    wmma::fragment<wmma::accumulator, 16, 16, 8, float> acc[2][4];
    #pragma unroll
    for (int i = 0; i < 2; i++)
        #pragma unroll
        for (int j = 0; j < 4; j++) wmma::fill_fragment(acc[i][j], 0.f);

    const int NK = K / BKT;

    auto issue = [&](int buf, int kt) {
        int k0 = kt * BKT;
        #pragma unroll
        for (int s = 0; s < 2; s++) {
            cp16(&As[buf * AS_STAGE + ar[s] * APAD + ac[s]],
                 A + (crow + ar[s]) * K + k0 + ac[s]);
            cp16(&Bs[buf * BS_STAGE + br[s] * BPAD + bc[s]],
                 Bw + (long long)(k0 + br[s]) * N + ccol + bc[s]);
        }
        asm volatile("cp.async.commit_group;\n");
    };

    issue(0, 0); issue(1, 1); issue(2, 2);

    for (int kt = 0; kt < NK; kt++) {
        if (kt <= NK - 3)      asm volatile("cp.async.wait_group 2;\n");
        else if (kt == NK - 2) asm volatile("cp.async.wait_group 1;\n");
        else                   asm volatile("cp.async.wait_group 0;\n");
        __syncthreads();
        if (kt + 3 < NK) issue((kt + 3) & 3, kt + 3);

        int buf = kt & 3;
        float* Ab = &As[buf * AS_STAGE];
        float* Bb = &Bs[buf * BS_STAGE];
        #pragma unroll
        for (int kk = 0; kk < BKT; kk += 8) {
            wmma::fragment<wmma::matrix_a, 16, 16, 8, wmma::precision::tf32, wmma::row_major> af[2];
            wmma::fragment<wmma::matrix_b, 16, 16, 8, wmma::precision::tf32, wmma::row_major> bf[4];
            #pragma unroll
            for (int i = 0; i < 2; i++) {
                wmma::load_matrix_sync(af[i], &Ab[(wm * 32 + i * 16) * APAD + kk], APAD);
                #pragma unroll
                for (int t = 0; t < af[i].num_elements; t++)
                    af[i].x[t] = wmma::__float_to_tf32(af[i].x[t]);
            }
            #pragma unroll
            for (int j = 0; j < 4; j++) {
                wmma::load_matrix_sync(bf[j], &Bb[kk * BPAD + wn * 64 + j * 16], BPAD);
                #pragma unroll
                for (int t = 0; t < bf[j].num_elements; t++)
                    bf[j].x[t] = wmma::__float_to_tf32(bf[j].x[t]);
            }
            #pragma unroll
            for (int i = 0; i < 2; i++)
                #pragma unroll
                for (int j = 0; j < 4; j++)
                    wmma::mma_sync(acc[i][j], af[i], bf[j], acc[i][j]);
        }
    }

    if (EPI == 0) {
        // dense per-frag store into [3][b][h][n][d]; 16-col blocks never cross
        // a head(32) or tensor(384) boundary; 16-row blocks stay in one window.
        #pragma unroll
        for (int i = 0; i < 2; i++) {
            long long m0 = crow + wm * 32 + i * 16;
            int b  = (int)(m0 >> 6);
            int n0 = (int)(m0 & 63);
            #pragma unroll
            for (int j = 0; j < 4; j++) {
                int c0 = ccol + wn * 64 + j * 16;
                int three = c0 / CDIM;
                int rem   = c0 - three * CDIM;
                int head  = rem >> 5;
                int dd0   = rem & 31;
                long long off = (long long)three * QKV_STRIDE +
                                (((long long)(b * HEADS + head)) * NTOK + n0) * HDIM + dd0;
                wmma::store_matrix_sync(&g_qkv[off], acc[i][j], HDIM, wmma::mem_row_major);
            }
        }
    } else {
        __syncthreads();                 // stage buffers now reusable
        float* ep = dsm + warp * 256;    // per-warp 16x16 patch
        #pragma unroll
        for (int i = 0; i < 2; i++) {
            #pragma unroll
            for (int j = 0; j < 4; j++) {
                wmma::store_matrix_sync(ep, acc[i][j], 16, wmma::mem_row_major);
                __syncwarp();
                long long m0 = crow + wm * 32 + i * 16;
                int c0 = ccol + wn * 64 + j * 16;
                #pragma unroll
                for (int e = 0; e < 8; e++) {
                    int idx = lane + e * 32;
                    int r = idx >> 4;
                    int c = idx & 15;
                    Cout[(m0 + r) * N + c0 + c] = ep[idx] + bias[c0 + c];
                }
                __syncwarp();
            }
        }
    }
}

// ---------------------------------------------------------------------------
// Fused attention, fp32, register-tiled. One block per (b,h), 256 threads.
// Adds qkv bias here (GEMM skips it).
// ---------------------------------------------------------------------------
__global__ __launch_bounds__(256)
void attn_kernel(const float* __restrict__ mask,
                 const float* __restrict__ logit_scale,
                 const float* __restrict__ qkv_b)
{
    int bh = blockIdx.x;
    int b = bh / HEADS;
    int h = bh - b * HEADS;

    __shared__ float qs[64 * 33];
    __shared__ float ks[64 * 33];
    __shared__ float vs[64 * 33];
    __shared__ float sc[64 * 65];

    int tid  = threadIdx.x;
    int warp = tid >> 5;
    int lane = tid & 31;
    int tr = tid >> 4;      // 0..15
    int tc = tid & 15;      // 0..15

    const float* qg = g_qkv + (long long)bh * (NTOK * HDIM);
    const float* kg = qg + QKV_STRIDE;
    const float* vg = kg + QKV_STRIDE;

    // v bias for this thread's column group (same for both loop iterations)
    int cb = (tid & 7) * 4;
    float4 bv4 = *(const float4*)&qkv_b[2 * CDIM + h * HDIM + cb];

    for (int e = tid; e < 512; e += 256) {
        int r = e >> 3;
        int c = (e & 7) * 4;
        float4 q4 = ((const float4*)qg)[e];
        float4 k4 = ((const float4*)kg)[e];
        float4 v4 = ((const float4*)vg)[e];
        float* dq = &qs[r * 33 + c];
        float* dk = &ks[r * 33 + c];
        float* dv = &vs[r * 33 + c];
        dq[0] = q4.x; dq[1] = q4.y; dq[2] = q4.z; dq[3] = q4.w;
        dk[0] = k4.x; dk[1] = k4.y; dk[2] = k4.z; dk[3] = k4.w;
        dv[0] = v4.x + bv4.x; dv[1] = v4.y + bv4.y;
        dv[2] = v4.z + bv4.z; dv[3] = v4.w + bv4.w;
    }
    __syncthreads();

    // add q/k bias + l2 normalize rows (warp per row chunk, lane = feature)
    float bq = qkv_b[h * HDIM + lane];
    float bk = qkv_b[CDIM + h * HDIM + lane];
    #pragma unroll
    for (int i = 0; i < 16; i++) {
        int r = warp * 16 + i;
        float* buf = (r < 64) ? &qs[r * 33] : &ks[(r - 64) * 33];
        float v = buf[lane] + ((r < 64) ? bq : bk);
        float ss = v * v;
        #pragma unroll
        for (int o = 16; o; o >>= 1) ss += __shfl_xor_sync(~0u, ss, o);
        buf[lane] = v / fmaxf(sqrtf(ss), 1e-12f);
    }
    __syncthreads();

    float scale = expf(fminf(logit_scale[h], 4.60517018598809f)); // ln(100)
    int w = b & (NWIN - 1);
    const float* mrow = mask + (long long)w * 4096;
    const float* brow = g_bias + h * 4096;

    // scores: 4x4 register tile; qi = tr+16i, kj = tc+16j (conflict-free LDS)
    {
        float acc[4][4];
        #pragma unroll
        for (int i = 0; i < 4; i++)
            #pragma unroll
            for (int j = 0; j < 4; j++) acc[i][j] = 0.f;
        #pragma unroll 4
        for (int l = 0; l < 32; l++) {
            float qv[4], kv[4];
            #pragma unroll
            for (int i = 0; i < 4; i++) qv[i] = qs[(tr + 16 * i) * 33 + l];
            #pragma unroll
            for (int j = 0; j < 4; j++) kv[j] = ks[(tc + 16 * j) * 33 + l];
            #pragma unroll
            for (int i = 0; i < 4; i++)
                #pragma unroll
                for (int j = 0; j < 4; j++) acc[i][j] += qv[i] * kv[j];
        }
        #pragma unroll
        for (int i = 0; i < 4; i++) {
            int qi = tr + 16 * i;
            #pragma unroll
            for (int j = 0; j < 4; j++) {
                int kj = tc + 16 * j;
                int e = qi * 64 + kj;
                sc[qi * 65 + kj] = fmaf(acc[i][j], scale, brow[e] + mrow[e]);
            }
        }
    }
    __syncthreads();

    // softmax: warp per 8 rows, lane covers 2 of 64 columns
    #pragma unroll
    for (int i = 0; i < 8; i++) {
        int qi = warp * 8 + i;
        float a = sc[qi * 65 + lane];
        float c = sc[qi * 65 + 32 + lane];
        float mx = fmaxf(a, c);
        #pragma unroll
        for (int o = 16; o; o >>= 1) mx = fmaxf(mx, __shfl_xor_sync(~0u, mx, o));
        a = __expf(a - mx);
        c = __expf(c - mx);
        float sm = a + c;
        #pragma unroll
        for (int o = 16; o; o >>= 1) sm += __shfl_xor_sync(~0u, sm, o);
        float inv = 1.f / sm;
        sc[qi * 65 + lane]      = a * inv;
        sc[qi * 65 + 32 + lane] = c * inv;
    }
    __syncthreads();

    // PV: 4x2 register tile; qi = tr+16i, dd = tc+16j
    {
        float acc[4][2];
        #pragma unroll
        for (int i = 0; i < 4; i++) { acc[i][0] = 0.f; acc[i][1] = 0.f; }
        #pragma unroll 4
        for (int kj = 0; kj < 64; kj++) {
            float pv[4], vv[2];
            #pragma unroll
            for (int i = 0; i < 4; i++) pv[i] = sc[(tr + 16 * i) * 65 + kj];
            vv[0] = vs[kj * 33 + tc];
            vv[1] = vs[kj * 33 + tc + 16];
            #pragma unroll
            for (int i = 0; i < 4; i++) {
                acc[i][0] += pv[i] * vv[0];
                acc[i][1] += pv[i] * vv[1];
            }
        }
        #pragma unroll
        for (int i = 0; i < 4; i++) {
            int qi = tr + 16 * i;
            long long rowo = ((long long)b * NTOK + qi) * CDIM + h * HDIM;
            g_att[rowo + tc]      = acc[i][0];
            g_att[rowo + tc + 16] = acc[i][1];
        }
    }
}

// ---------------------------------------------------------------------------
extern "C" void kernel_launch(void* const* d_in, const int* in_sizes, int n_in,
                              void* d_out, int out_size)
{
    const float* x           = (const float*)d_in[0];
    const float* mask        = (const float*)d_in[1];
    const float* qkv_w       = (const float*)d_in[2];
    const float* qkv_b       = (const float*)d_in[3];
    const float* proj_w      = (const float*)d_in[4];
    const float* proj_b      = (const float*)d_in[5];
    const float* logit_scale = (const float*)d_in[6];
    const float* cpb_w1      = (const float*)d_in[7];
    const float* cpb_b1      = (const float*)d_in[8];
    const float* cpb_w2      = (const float*)d_in[9];
    const float* rel_table   = (const float*)d_in[10];
    const int*   rel_index   = (const int*)d_in[11];
    float* out = (float*)d_out;

    static int attr_done = 0;
    if (!attr_done) {
        cudaFuncSetAttribute(tgemm<0>, cudaFuncAttributeMaxDynamicSharedMemorySize, GEMM_SMEM_BYTES);
        cudaFuncSetAttribute(tgemm<1>, cudaFuncAttributeMaxDynamicSharedMemorySize, GEMM_SMEM_BYTES);
        attr_done = 1;
    }

    cpb_tab_kernel<<<16, 256>>>(rel_table, cpb_w1, cpb_b1, cpb_w2);
    cpb_gather_kernel<<<192, 256>>>(rel_index);

    // qkv gemm: [262144,384] x [384,1152]
    {
        dim3 grid(QKV_N / BN, M1 / BM);
        tgemm<0><<<grid, 256, GEMM_SMEM_BYTES>>>(x, qkv_w, nullptr, nullptr, QKV_N, CDIM);
    }

    attn_kernel<<<BWIN * HEADS, 256>>>(mask, logit_scale, qkv_b);

    // proj gemm: [262144,384] x [384,384]
    {
        dim3 grid(CDIM / BN, M1 / BM);
        tgemm<1><<<grid, 256, GEMM_SMEM_BYTES>>>(nullptr, proj_w, proj_b, out, CDIM, CDIM);
    }
}

// round 5
// speedup vs baseline: 3.2552x; 1.6440x over previous
#include <cuda_runtime.h>
#include <cuda_fp16.h>
#include <cstdint>
#include <mma.h>
#include <math.h>

using namespace nvcuda;

// ---------------------------------------------------------------------------
// WindowAttentionV2: b=4096 windows, n=64 tokens, C=384, H=12 heads, d=32
// ---------------------------------------------------------------------------

#define BWIN   4096
#define NTOK   64
#define CDIM   384
#define HEADS  12
#define HDIM   32
#define NWIN   1024
#define M1     (BWIN * NTOK)          // 262144 rows
#define QKV_N  (3 * CDIM)             // 1152
#define QKV_STRIDE (BWIN * HEADS * NTOK * HDIM)

// Scratch (device globals; no allocations allowed)
__device__ float  g_qkv[3ll * QKV_STRIDE];          // [3][b][h][n][d] (no bias)
__device__ float  g_att[(long long)M1 * CDIM];      // [b*n][h*32+d]
__device__ __half g_xh[(long long)M1 * CDIM];       // fp16 copy of x
__device__ __half g_wh[CDIM * QKV_N];               // fp16 copy of qkv_w
__device__ float  g_tab[4096 * HEADS];
__device__ float  g_bias[HEADS * NTOK * NTOK];

// ---------------------------------------------------------------------------
__global__ void cpb_tab_kernel(const float* __restrict__ table,
                               const float* __restrict__ w1,
                               const float* __restrict__ b1,
                               const float* __restrict__ w2)
{
    int i = blockIdx.x * blockDim.x + threadIdx.x;
    if (i >= 4096) return;
    float t0 = table[i * 2 + 0];
    float t1 = table[i * 2 + 1];
    float out[HEADS];
    #pragma unroll
    for (int h = 0; h < HEADS; h++) out[h] = 0.f;
    for (int j = 0; j < 512; j++) {
        float hd = fmaxf(fmaf(t0, w1[j], fmaf(t1, w1[512 + j], b1[j])), 0.f);
        #pragma unroll
        for (int h = 0; h < HEADS; h++) out[h] += hd * w2[j * HEADS + h];
    }
    #pragma unroll
    for (int h = 0; h < HEADS; h++) g_tab[i * HEADS + h] = out[h];
}

__global__ void cpb_gather_kernel(const int* __restrict__ index)
{
    int e = blockIdx.x * blockDim.x + threadIdx.x;
    if (e >= HEADS * 4096) return;
    int h = e / 4096;
    int qk = e % 4096;
    float v = g_tab[index[qk] * HEADS + h];
    g_bias[e] = 16.f / (1.f + expf(-v));
}

// ---------------------------------------------------------------------------
// fp32 -> fp16 converters
// ---------------------------------------------------------------------------
__global__ __launch_bounds__(256) void convert_x_kernel(const float* __restrict__ x)
{
    long long n4 = (long long)M1 * CDIM / 4;
    long long stride = (long long)gridDim.x * blockDim.x;
    for (long long i = blockIdx.x * blockDim.x + threadIdx.x; i < n4; i += stride) {
        float4 v = ((const float4*)x)[i];
        __half2* dst = (__half2*)g_xh;
        dst[2 * i + 0] = __floats2half2_rn(v.x, v.y);
        dst[2 * i + 1] = __floats2half2_rn(v.z, v.w);
    }
}

__global__ __launch_bounds__(256) void convert_w_kernel(const float* __restrict__ w)
{
    int n4 = CDIM * QKV_N / 4;
    int i = blockIdx.x * blockDim.x + threadIdx.x;
    if (i >= n4) return;
    float4 v = ((const float4*)w)[i];
    __half2* dst = (__half2*)g_wh;
    dst[2 * i + 0] = __floats2half2_rn(v.x, v.y);
    dst[2 * i + 1] = __floats2half2_rn(v.z, v.w);
}

// ---------------------------------------------------------------------------
// fp16 GEMM (qkv): 128x128 tile, BK=32, 4-stage cp.async ring.
// 8 warps; warp (wm,wn) owns 32x64 = 2x4 m16n16k16 frags, fp32 accum.
// Dense frag store into g_qkv [3][b][h][n][d] (no bias; added in attention).
// ---------------------------------------------------------------------------
#define HBK 32
#define HAPAD 40      // halves; 80B rows
#define HBPAD 136     // halves; 272B rows
#define HAS_STAGE (128 * HAPAD)    // 5120 halves
#define HBS_STAGE (HBK * HBPAD)    // 4352 halves
#define HSTAGES 4
#define HGEMM_SMEM_BYTES (HSTAGES * (HAS_STAGE + HBS_STAGE) * 2)   // 75776

__device__ __forceinline__ void cp16(void* s, const void* g)
{
    unsigned int sa = (unsigned int)__cvta_generic_to_shared(s);
    asm volatile("cp.async.cg.shared.global [%0], [%1], 16;\n" :: "r"(sa), "l"(g));
}

__global__ __launch_bounds__(256)
void hgemm_qkv()
{
    extern __shared__ __half hsm[];
    __half* As = hsm;
    __half* Bs = hsm + HSTAGES * HAS_STAGE;

    const int N = QKV_N, K = CDIM;
    int tid  = threadIdx.x;
    int warp = tid >> 5;
    int wm = warp >> 1;
    int wn = warp & 1;
    long long crow = (long long)blockIdx.y * 128;
    int ccol = blockIdx.x * 128;

    int ar[2], ac[2], br[2], bc[2];
    #pragma unroll
    for (int s = 0; s < 2; s++) {
        int i = tid + s * 256;
        ar[s] = i >> 2;  ac[s] = (i & 3) * 8;     // A: 128 rows x 32 halves
        br[s] = i >> 4;  bc[s] = (i & 15) * 8;    // B: 32 rows x 128 halves
    }

    wmma::fragment<wmma::accumulator, 16, 16, 16, float> acc[2][4];
    #pragma unroll
    for (int i = 0; i < 2; i++)
        #pragma unroll
        for (int j = 0; j < 4; j++) wmma::fill_fragment(acc[i][j], 0.f);

    const int NK = K / HBK;   // 12

    auto issue = [&](int buf, int kt) {
        int k0 = kt * HBK;
        #pragma unroll
        for (int s = 0; s < 2; s++) {
            cp16(&As[buf * HAS_STAGE + ar[s] * HAPAD + ac[s]],
                 g_xh + (crow + ar[s]) * K + k0 + ac[s]);
            cp16(&Bs[buf * HBS_STAGE + br[s] * HBPAD + bc[s]],
                 g_wh + (long long)(k0 + br[s]) * N + ccol + bc[s]);
        }
        asm volatile("cp.async.commit_group;\n");
    };

    issue(0, 0); issue(1, 1); issue(2, 2);

    for (int kt = 0; kt < NK; kt++) {
        if (kt <= NK - 3)      asm volatile("cp.async.wait_group 2;\n");
        else if (kt == NK - 2) asm volatile("cp.async.wait_group 1;\n");
        else                   asm volatile("cp.async.wait_group 0;\n");
        __syncthreads();
        if (kt + 3 < NK) issue((kt + 3) & 3, kt + 3);

        int buf = kt & 3;
        __half* Ab = &As[buf * HAS_STAGE];
        __half* Bb = &Bs[buf * HBS_STAGE];
        #pragma unroll
        for (int kk = 0; kk < HBK; kk += 16) {
            wmma::fragment<wmma::matrix_a, 16, 16, 16, __half, wmma::row_major> af[2];
            wmma::fragment<wmma::matrix_b, 16, 16, 16, __half, wmma::row_major> bf[4];
            #pragma unroll
            for (int i = 0; i < 2; i++)
                wmma::load_matrix_sync(af[i], &Ab[(wm * 32 + i * 16) * HAPAD + kk], HAPAD);
            #pragma unroll
            for (int j = 0; j < 4; j++)
                wmma::load_matrix_sync(bf[j], &Bb[kk * HBPAD + wn * 64 + j * 16], HBPAD);
            #pragma unroll
            for (int i = 0; i < 2; i++)
                #pragma unroll
                for (int j = 0; j < 4; j++)
                    wmma::mma_sync(acc[i][j], af[i], bf[j], acc[i][j]);
        }
    }

    // dense per-frag store into [3][b][h][n][d]
    #pragma unroll
    for (int i = 0; i < 2; i++) {
        long long m0 = crow + wm * 32 + i * 16;
        int b  = (int)(m0 >> 6);
        int n0 = (int)(m0 & 63);
        #pragma unroll
        for (int j = 0; j < 4; j++) {
            int c0 = ccol + wn * 64 + j * 16;
            int three = c0 / CDIM;
            int rem   = c0 - three * CDIM;
            int head  = rem >> 5;
            int dd0   = rem & 31;
            long long off = (long long)three * QKV_STRIDE +
                            (((long long)(b * HEADS + head)) * NTOK + n0) * HDIM + dd0;
            wmma::store_matrix_sync(&g_qkv[off], acc[i][j], HDIM, wmma::mem_row_major);
        }
    }
}

// ---------------------------------------------------------------------------
// tf32 GEMM for proj (fp32 A from g_att): 128x128, BK=16, 4-stage ring.
// ---------------------------------------------------------------------------
#define BM 128
#define BN 128
#define BKT 16
#define APAD 20
#define BPAD 132
#define NSTAGE 4
#define AS_STAGE (BM * APAD)
#define BS_STAGE (BKT * BPAD)
#define GEMM_SMEM_BYTES (NSTAGE * (AS_STAGE + BS_STAGE) * 4)   // 74752

__global__ __launch_bounds__(256)
void tgemm_proj(const float* __restrict__ Bw,
                const float* __restrict__ bias,
                float* __restrict__ Cout)
{
    extern __shared__ float dsm[];
    float* As = dsm;
    float* Bs = dsm + NSTAGE * AS_STAGE;

    const float* A = (const float*)g_att;
    const int N = CDIM, K = CDIM;

    int tid  = threadIdx.x;
    int lane = tid & 31;
    int warp = tid >> 5;
    int wm = warp >> 1;
    int wn = warp & 1;
    long long crow = (long long)blockIdx.y * BM;
    int ccol = blockIdx.x * BN;

    int ar[2], ac[2], br[2], bc[2];
    #pragma unroll
    for (int s = 0; s < 2; s++) {
        int i = tid + s * 256;
        ar[s] = i >> 2;  ac[s] = (i & 3) * 4;
        br[s] = i >> 5;  bc[s] = (i & 31) * 4;
    }

    wmma::fragment<wmma::accumulator, 16, 16, 8, float> acc[2][4];
    #pragma unroll
    for (int i = 0; i < 2; i++)
        #pragma unroll
        for (int j = 0; j < 4; j++) wmma::fill_fragment(acc[i][j], 0.f);

    const int NK = K / BKT;

    auto issue = [&](int buf, int kt) {
        int k0 = kt * BKT;
        #pragma unroll
        for (int s = 0; s < 2; s++) {
            cp16(&As[buf * AS_STAGE + ar[s] * APAD + ac[s]],
                 A + (crow + ar[s]) * K + k0 + ac[s]);
            cp16(&Bs[buf * BS_STAGE + br[s] * BPAD + bc[s]],
                 Bw + (long long)(k0 + br[s]) * N + ccol + bc[s]);
        }
        asm volatile("cp.async.commit_group;\n");
    };

    issue(0, 0); issue(1, 1); issue(2, 2);

    for (int kt = 0; kt < NK; kt++) {
        if (kt <= NK - 3)      asm volatile("cp.async.wait_group 2;\n");
        else if (kt == NK - 2) asm volatile("cp.async.wait_group 1;\n");
        else                   asm volatile("cp.async.wait_group 0;\n");
        __syncthreads();
        if (kt + 3 < NK) issue((kt + 3) & 3, kt + 3);

        int buf = kt & 3;
        float* Ab = &As[buf * AS_STAGE];
        float* Bb = &Bs[buf * BS_STAGE];
        #pragma unroll
        for (int kk = 0; kk < BKT; kk += 8) {
            wmma::fragment<wmma::matrix_a, 16, 16, 8, wmma::precision::tf32, wmma::row_major> af[2];
            wmma::fragment<wmma::matrix_b, 16, 16, 8, wmma::precision::tf32, wmma::row_major> bf[4];
            #pragma unroll
            for (int i = 0; i < 2; i++) {
                wmma::load_matrix_sync(af[i], &Ab[(wm * 32 + i * 16) * APAD + kk], APAD);
                #pragma unroll
                for (int t = 0; t < af[i].num_elements; t++)
                    af[i].x[t] = wmma::__float_to_tf32(af[i].x[t]);
            }
            #pragma unroll
            for (int j = 0; j < 4; j++) {
                wmma::load_matrix_sync(bf[j], &Bb[kk * BPAD + wn * 64 + j * 16], BPAD);
                #pragma unroll
                for (int t = 0; t < bf[j].num_elements; t++)
                    bf[j].x[t] = wmma::__float_to_tf32(bf[j].x[t]);
            }
            #pragma unroll
            for (int i = 0; i < 2; i++)
                #pragma unroll
                for (int j = 0; j < 4; j++)
                    wmma::mma_sync(acc[i][j], af[i], bf[j], acc[i][j]);
        }
    }

    __syncthreads();
    float* ep = dsm + warp * 256;
    #pragma unroll
    for (int i = 0; i < 2; i++) {
        #pragma unroll
        for (int j = 0; j < 4; j++) {
            wmma::store_matrix_sync(ep, acc[i][j], 16, wmma::mem_row_major);
            __syncwarp();
            long long m0 = crow + wm * 32 + i * 16;
            int c0 = ccol + wn * 64 + j * 16;
            #pragma unroll
            for (int e = 0; e < 8; e++) {
                int idx = lane + e * 32;
                int r = idx >> 4;
                int c = idx & 15;
                Cout[(m0 + r) * N + c0 + c] = ep[idx] + bias[c0 + c];
            }
            __syncwarp();
        }
    }
}

// ---------------------------------------------------------------------------
// Fused attention, fp32, register-tiled. One block per (b,h), 256 threads.
// ---------------------------------------------------------------------------
__global__ __launch_bounds__(256)
void attn_kernel(const float* __restrict__ mask,
                 const float* __restrict__ logit_scale,
                 const float* __restrict__ qkv_b)
{
    int bh = blockIdx.x;
    int b = bh / HEADS;
    int h = bh - b * HEADS;

    __shared__ float qs[64 * 33];
    __shared__ float ks[64 * 33];
    __shared__ float vs[64 * 33];
    __shared__ float sc[64 * 65];

    int tid  = threadIdx.x;
    int warp = tid >> 5;
    int lane = tid & 31;
    int tr = tid >> 4;
    int tc = tid & 15;

    const float* qg = g_qkv + (long long)bh * (NTOK * HDIM);
    const float* kg = qg + QKV_STRIDE;
    const float* vg = kg + QKV_STRIDE;

    int cb = (tid & 7) * 4;
    float4 bv4 = *(const float4*)&qkv_b[2 * CDIM + h * HDIM + cb];

    for (int e = tid; e < 512; e += 256) {
        int r = e >> 3;
        int c = (e & 7) * 4;
        float4 q4 = ((const float4*)qg)[e];
        float4 k4 = ((const float4*)kg)[e];
        float4 v4 = ((const float4*)vg)[e];
        float* dq = &qs[r * 33 + c];
        float* dk = &ks[r * 33 + c];
        float* dv = &vs[r * 33 + c];
        dq[0] = q4.x; dq[1] = q4.y; dq[2] = q4.z; dq[3] = q4.w;
        dk[0] = k4.x; dk[1] = k4.y; dk[2] = k4.z; dk[3] = k4.w;
        dv[0] = v4.x + bv4.x; dv[1] = v4.y + bv4.y;
        dv[2] = v4.z + bv4.z; dv[3] = v4.w + bv4.w;
    }
    __syncthreads();

    float bq = qkv_b[h * HDIM + lane];
    float bk = qkv_b[CDIM + h * HDIM + lane];
    #pragma unroll
    for (int i = 0; i < 16; i++) {
        int r = warp * 16 + i;
        float* buf = (r < 64) ? &qs[r * 33] : &ks[(r - 64) * 33];
        float v = buf[lane] + ((r < 64) ? bq : bk);
        float ss = v * v;
        #pragma unroll
        for (int o = 16; o; o >>= 1) ss += __shfl_xor_sync(~0u, ss, o);
        buf[lane] = v / fmaxf(sqrtf(ss), 1e-12f);
    }
    __syncthreads();

    float scale = expf(fminf(logit_scale[h], 4.60517018598809f)); // ln(100)
    int w = b & (NWIN - 1);
    const float* mrow = mask + (long long)w * 4096;
    const float* brow = g_bias + h * 4096;

    {
        float acc[4][4];
        #pragma unroll
        for (int i = 0; i < 4; i++)
            #pragma unroll
            for (int j = 0; j < 4; j++) acc[i][j] = 0.f;
        #pragma unroll 4
        for (int l = 0; l < 32; l++) {
            float qv[4], kv[4];
            #pragma unroll
            for (int i = 0; i < 4; i++) qv[i] = qs[(tr + 16 * i) * 33 + l];
            #pragma unroll
            for (int j = 0; j < 4; j++) kv[j] = ks[(tc + 16 * j) * 33 + l];
            #pragma unroll
            for (int i = 0; i < 4; i++)
                #pragma unroll
                for (int j = 0; j < 4; j++) acc[i][j] += qv[i] * kv[j];
        }
        #pragma unroll
        for (int i = 0; i < 4; i++) {
            int qi = tr + 16 * i;
            #pragma unroll
            for (int j = 0; j < 4; j++) {
                int kj = tc + 16 * j;
                int e = qi * 64 + kj;
                sc[qi * 65 + kj] = fmaf(acc[i][j], scale, brow[e] + mrow[e]);
            }
        }
    }
    __syncthreads();

    #pragma unroll
    for (int i = 0; i < 8; i++) {
        int qi = warp * 8 + i;
        float a = sc[qi * 65 + lane];
        float c = sc[qi * 65 + 32 + lane];
        float mx = fmaxf(a, c);
        #pragma unroll
        for (int o = 16; o; o >>= 1) mx = fmaxf(mx, __shfl_xor_sync(~0u, mx, o));
        a = __expf(a - mx);
        c = __expf(c - mx);
        float sm = a + c;
        #pragma unroll
        for (int o = 16; o; o >>= 1) sm += __shfl_xor_sync(~0u, sm, o);
        float inv = 1.f / sm;
        sc[qi * 65 + lane]      = a * inv;
        sc[qi * 65 + 32 + lane] = c * inv;
    }
    __syncthreads();

    {
        float acc[4][2];
        #pragma unroll
        for (int i = 0; i < 4; i++) { acc[i][0] = 0.f; acc[i][1] = 0.f; }
        #pragma unroll 4
        for (int kj = 0; kj < 64; kj++) {
            float pv[4], vv[2];
            #pragma unroll
            for (int i = 0; i < 4; i++) pv[i] = sc[(tr + 16 * i) * 65 + kj];
            vv[0] = vs[kj * 33 + tc];
            vv[1] = vs[kj * 33 + tc + 16];
            #pragma unroll
            for (int i = 0; i < 4; i++) {
                acc[i][0] += pv[i] * vv[0];
                acc[i][1] += pv[i] * vv[1];
            }
        }
        #pragma unroll
        for (int i = 0; i < 4; i++) {
            int qi = tr + 16 * i;
            long long rowo = ((long long)b * NTOK + qi) * CDIM + h * HDIM;
            g_att[rowo + tc]      = acc[i][0];
            g_att[rowo + tc + 16] = acc[i][1];
        }
    }
}

// ---------------------------------------------------------------------------
extern "C" void kernel_launch(void* const* d_in, const int* in_sizes, int n_in,
                              void* d_out, int out_size)
{
    const float* x           = (const float*)d_in[0];
    const float* mask        = (const float*)d_in[1];
    const float* qkv_w       = (const float*)d_in[2];
    const float* qkv_b       = (const float*)d_in[3];
    const float* proj_w      = (const float*)d_in[4];
    const float* proj_b      = (const float*)d_in[5];
    const float* logit_scale = (const float*)d_in[6];
    const float* cpb_w1      = (const float*)d_in[7];
    const float* cpb_b1      = (const float*)d_in[8];
    const float* cpb_w2      = (const float*)d_in[9];
    const float* rel_table   = (const float*)d_in[10];
    const int*   rel_index   = (const int*)d_in[11];
    float* out = (float*)d_out;

    static int attr_done = 0;
    if (!attr_done) {
        cudaFuncSetAttribute(hgemm_qkv,  cudaFuncAttributeMaxDynamicSharedMemorySize, HGEMM_SMEM_BYTES);
        cudaFuncSetAttribute(tgemm_proj, cudaFuncAttributeMaxDynamicSharedMemorySize, GEMM_SMEM_BYTES);
        attr_done = 1;
    }

    // fp32 -> fp16 copies of x and qkv_w
    convert_x_kernel<<<2048, 256>>>(x);
    convert_w_kernel<<<432, 256>>>(qkv_w);

    cpb_tab_kernel<<<16, 256>>>(rel_table, cpb_w1, cpb_b1, cpb_w2);
    cpb_gather_kernel<<<192, 256>>>(rel_index);

    // qkv gemm: [262144,384] x [384,1152], fp16 in / fp32 accum
    {
        dim3 grid(QKV_N / 128, M1 / 128);
        hgemm_qkv<<<grid, 256, HGEMM_SMEM_BYTES>>>();
    }

    attn_kernel<<<BWIN * HEADS, 256>>>(mask, logit_scale, qkv_b);

    // proj gemm: [262144,384] x [384,384], tf32
    {
        dim3 grid(CDIM / BN, M1 / BM);
        tgemm_proj<<<grid, 256, GEMM_SMEM_BYTES>>>(proj_w, proj_b, out);
    }
}

// round 6
// speedup vs baseline: 4.4094x; 1.3546x over previous
#include <cuda_runtime.h>
#include <cuda_fp16.h>
#include <cstdint>
#include <mma.h>
#include <math.h>

using namespace nvcuda;

// ---------------------------------------------------------------------------
// WindowAttentionV2: b=4096 windows, n=64 tokens, C=384, H=12 heads, d=32
// ---------------------------------------------------------------------------

#define BWIN   4096
#define NTOK   64
#define CDIM   384
#define HEADS  12
#define HDIM   32
#define NWIN   1024
#define M1     (BWIN * NTOK)          // 262144 rows
#define QKV_N  (3 * CDIM)             // 1152
#define QKV_STRIDE (BWIN * HEADS * NTOK * HDIM)

// Scratch (device globals; no allocations allowed)
__device__ float  g_qkv[3ll * QKV_STRIDE];          // [3][b][h][n][d] (no bias)
__device__ __half g_att[(long long)M1 * CDIM];      // fp16 attention output
__device__ __half g_xh[(long long)M1 * CDIM];       // fp16 copy of x
__device__ __half g_wh[CDIM * QKV_N];               // fp16 copy of qkv_w
__device__ __half g_wph[CDIM * CDIM];               // fp16 copy of proj_w
__device__ float  g_tab[4096 * HEADS];
__device__ float  g_bias[HEADS * NTOK * NTOK];

// ---------------------------------------------------------------------------
__global__ void cpb_tab_kernel(const float* __restrict__ table,
                               const float* __restrict__ w1,
                               const float* __restrict__ b1,
                               const float* __restrict__ w2)
{
    int i = blockIdx.x * blockDim.x + threadIdx.x;
    if (i >= 4096) return;
    float t0 = table[i * 2 + 0];
    float t1 = table[i * 2 + 1];
    float out[HEADS];
    #pragma unroll
    for (int h = 0; h < HEADS; h++) out[h] = 0.f;
    for (int j = 0; j < 512; j++) {
        float hd = fmaxf(fmaf(t0, w1[j], fmaf(t1, w1[512 + j], b1[j])), 0.f);
        #pragma unroll
        for (int h = 0; h < HEADS; h++) out[h] += hd * w2[j * HEADS + h];
    }
    #pragma unroll
    for (int h = 0; h < HEADS; h++) g_tab[i * HEADS + h] = out[h];
}

__global__ void cpb_gather_kernel(const int* __restrict__ index)
{
    int e = blockIdx.x * blockDim.x + threadIdx.x;
    if (e >= HEADS * 4096) return;
    int h = e / 4096;
    int qk = e % 4096;
    float v = g_tab[index[qk] * HEADS + h];
    g_bias[e] = 16.f / (1.f + expf(-v));
}

// ---------------------------------------------------------------------------
// fp32 -> fp16 converters
// ---------------------------------------------------------------------------
__global__ __launch_bounds__(256) void convert_x_kernel(const float* __restrict__ x)
{
    long long n4 = (long long)M1 * CDIM / 4;
    long long stride = (long long)gridDim.x * blockDim.x;
    for (long long i = blockIdx.x * blockDim.x + threadIdx.x; i < n4; i += stride) {
        float4 v = ((const float4*)x)[i];
        __half2* dst = (__half2*)g_xh;
        dst[2 * i + 0] = __floats2half2_rn(v.x, v.y);
        dst[2 * i + 1] = __floats2half2_rn(v.z, v.w);
    }
}

__global__ __launch_bounds__(256) void convert_w_kernel(const float* __restrict__ w,
                                                        int n4, __half* dst_h)
{
    int i = blockIdx.x * blockDim.x + threadIdx.x;
    if (i >= n4) return;
    float4 v = ((const float4*)w)[i];
    __half2* dst = (__half2*)dst_h;
    dst[2 * i + 0] = __floats2half2_rn(v.x, v.y);
    dst[2 * i + 1] = __floats2half2_rn(v.z, v.w);
}

// ---------------------------------------------------------------------------
// fp16 GEMM cores: 128x128 tile, BK=32, 4-stage cp.async ring, fp32 accum.
// ---------------------------------------------------------------------------
#define HBK 32
#define HAPAD 40      // halves; 80B rows
#define HBPAD 136     // halves; 272B rows
#define HAS_STAGE (128 * HAPAD)    // 5120 halves
#define HBS_STAGE (HBK * HBPAD)    // 4352 halves
#define HSTAGES 4
#define HGEMM_SMEM_BYTES (HSTAGES * (HAS_STAGE + HBS_STAGE) * 2)   // 75776

__device__ __forceinline__ void cp16(void* s, const void* g)
{
    unsigned int sa = (unsigned int)__cvta_generic_to_shared(s);
    asm volatile("cp.async.cg.shared.global [%0], [%1], 16;\n" :: "r"(sa), "l"(g));
}

// qkv: A = g_xh, B = g_wh, N=1152; dense frag store into g_qkv (fp32)
__global__ __launch_bounds__(256)
void hgemm_qkv()
{
    extern __shared__ __half hsm[];
    __half* As = hsm;
    __half* Bs = hsm + HSTAGES * HAS_STAGE;

    const int N = QKV_N, K = CDIM;
    int tid  = threadIdx.x;
    int warp = tid >> 5;
    int wm = warp >> 1;
    int wn = warp & 1;
    long long crow = (long long)blockIdx.y * 128;
    int ccol = blockIdx.x * 128;

    int ar[2], ac[2], br[2], bc[2];
    #pragma unroll
    for (int s = 0; s < 2; s++) {
        int i = tid + s * 256;
        ar[s] = i >> 2;  ac[s] = (i & 3) * 8;
        br[s] = i >> 4;  bc[s] = (i & 15) * 8;
    }

    wmma::fragment<wmma::accumulator, 16, 16, 16, float> acc[2][4];
    #pragma unroll
    for (int i = 0; i < 2; i++)
        #pragma unroll
        for (int j = 0; j < 4; j++) wmma::fill_fragment(acc[i][j], 0.f);

    const int NK = K / HBK;   // 12

    auto issue = [&](int buf, int kt) {
        int k0 = kt * HBK;
        #pragma unroll
        for (int s = 0; s < 2; s++) {
            cp16(&As[buf * HAS_STAGE + ar[s] * HAPAD + ac[s]],
                 g_xh + (crow + ar[s]) * K + k0 + ac[s]);
            cp16(&Bs[buf * HBS_STAGE + br[s] * HBPAD + bc[s]],
                 g_wh + (long long)(k0 + br[s]) * N + ccol + bc[s]);
        }
        asm volatile("cp.async.commit_group;\n");
    };

    issue(0, 0); issue(1, 1); issue(2, 2);

    for (int kt = 0; kt < NK; kt++) {
        if (kt <= NK - 3)      asm volatile("cp.async.wait_group 2;\n");
        else if (kt == NK - 2) asm volatile("cp.async.wait_group 1;\n");
        else                   asm volatile("cp.async.wait_group 0;\n");
        __syncthreads();
        if (kt + 3 < NK) issue((kt + 3) & 3, kt + 3);

        int buf = kt & 3;
        __half* Ab = &As[buf * HAS_STAGE];
        __half* Bb = &Bs[buf * HBS_STAGE];
        #pragma unroll
        for (int kk = 0; kk < HBK; kk += 16) {
            wmma::fragment<wmma::matrix_a, 16, 16, 16, __half, wmma::row_major> af[2];
            wmma::fragment<wmma::matrix_b, 16, 16, 16, __half, wmma::row_major> bf[4];
            #pragma unroll
            for (int i = 0; i < 2; i++)
                wmma::load_matrix_sync(af[i], &Ab[(wm * 32 + i * 16) * HAPAD + kk], HAPAD);
            #pragma unroll
            for (int j = 0; j < 4; j++)
                wmma::load_matrix_sync(bf[j], &Bb[kk * HBPAD + wn * 64 + j * 16], HBPAD);
            #pragma unroll
            for (int i = 0; i < 2; i++)
                #pragma unroll
                for (int j = 0; j < 4; j++)
                    wmma::mma_sync(acc[i][j], af[i], bf[j], acc[i][j]);
        }
    }

    #pragma unroll
    for (int i = 0; i < 2; i++) {
        long long m0 = crow + wm * 32 + i * 16;
        int b  = (int)(m0 >> 6);
        int n0 = (int)(m0 & 63);
        #pragma unroll
        for (int j = 0; j < 4; j++) {
            int c0 = ccol + wn * 64 + j * 16;
            int three = c0 / CDIM;
            int rem   = c0 - three * CDIM;
            int head  = rem >> 5;
            int dd0   = rem & 31;
            long long off = (long long)three * QKV_STRIDE +
                            (((long long)(b * HEADS + head)) * NTOK + n0) * HDIM + dd0;
            wmma::store_matrix_sync(&g_qkv[off], acc[i][j], HDIM, wmma::mem_row_major);
        }
    }
}

// proj: A = g_att (half), B = g_wph, N=384; +bias, fp32 dense out
__global__ __launch_bounds__(256)
void hgemm_proj(const float* __restrict__ bias, float* __restrict__ Cout)
{
    extern __shared__ __half hsm[];
    __half* As = hsm;
    __half* Bs = hsm + HSTAGES * HAS_STAGE;

    const int N = CDIM, K = CDIM;
    int tid  = threadIdx.x;
    int lane = tid & 31;
    int warp = tid >> 5;
    int wm = warp >> 1;
    int wn = warp & 1;
    long long crow = (long long)blockIdx.y * 128;
    int ccol = blockIdx.x * 128;

    int ar[2], ac[2], br[2], bc[2];
    #pragma unroll
    for (int s = 0; s < 2; s++) {
        int i = tid + s * 256;
        ar[s] = i >> 2;  ac[s] = (i & 3) * 8;
        br[s] = i >> 4;  bc[s] = (i & 15) * 8;
    }

    wmma::fragment<wmma::accumulator, 16, 16, 16, float> acc[2][4];
    #pragma unroll
    for (int i = 0; i < 2; i++)
        #pragma unroll
        for (int j = 0; j < 4; j++) wmma::fill_fragment(acc[i][j], 0.f);

    const int NK = K / HBK;   // 12

    auto issue = [&](int buf, int kt) {
        int k0 = kt * HBK;
        #pragma unroll
        for (int s = 0; s < 2; s++) {
            cp16(&As[buf * HAS_STAGE + ar[s] * HAPAD + ac[s]],
                 g_att + (crow + ar[s]) * K + k0 + ac[s]);
            cp16(&Bs[buf * HBS_STAGE + br[s] * HBPAD + bc[s]],
                 g_wph + (long long)(k0 + br[s]) * N + ccol + bc[s]);
        }
        asm volatile("cp.async.commit_group;\n");
    };

    issue(0, 0); issue(1, 1); issue(2, 2);

    for (int kt = 0; kt < NK; kt++) {
        if (kt <= NK - 3)      asm volatile("cp.async.wait_group 2;\n");
        else if (kt == NK - 2) asm volatile("cp.async.wait_group 1;\n");
        else                   asm volatile("cp.async.wait_group 0;\n");
        __syncthreads();
        if (kt + 3 < NK) issue((kt + 3) & 3, kt + 3);

        int buf = kt & 3;
        __half* Ab = &As[buf * HAS_STAGE];
        __half* Bb = &Bs[buf * HBS_STAGE];
        #pragma unroll
        for (int kk = 0; kk < HBK; kk += 16) {
            wmma::fragment<wmma::matrix_a, 16, 16, 16, __half, wmma::row_major> af[2];
            wmma::fragment<wmma::matrix_b, 16, 16, 16, __half, wmma::row_major> bf[4];
            #pragma unroll
            for (int i = 0; i < 2; i++)
                wmma::load_matrix_sync(af[i], &Ab[(wm * 32 + i * 16) * HAPAD + kk], HAPAD);
            #pragma unroll
            for (int j = 0; j < 4; j++)
                wmma::load_matrix_sync(bf[j], &Bb[kk * HBPAD + wn * 64 + j * 16], HBPAD);
            #pragma unroll
            for (int i = 0; i < 2; i++)
                #pragma unroll
                for (int j = 0; j < 4; j++)
                    wmma::mma_sync(acc[i][j], af[i], bf[j], acc[i][j]);
        }
    }

    __syncthreads();
    float* ep = ((float*)hsm) + warp * 256;
    #pragma unroll
    for (int i = 0; i < 2; i++) {
        #pragma unroll
        for (int j = 0; j < 4; j++) {
            wmma::store_matrix_sync(ep, acc[i][j], 16, wmma::mem_row_major);
            __syncwarp();
            long long m0 = crow + wm * 32 + i * 16;
            int c0 = ccol + wn * 64 + j * 16;
            #pragma unroll
            for (int e = 0; e < 8; e++) {
                int idx = lane + e * 32;
                int r = idx >> 4;
                int c = idx & 15;
                Cout[(m0 + r) * N + c0 + c] = ep[idx] + bias[c0 + c];
            }
            __syncwarp();
        }
    }
}

// ---------------------------------------------------------------------------
// Fused attention, fp32 compute. One block per (b,h), 256 threads.
// qs/ks stride 34 (float2 along l, conflict-free LDS.64); sc stride 66.
// Writes g_att as fp16.
// ---------------------------------------------------------------------------
#define QKS 34
#define SCS 66

__global__ __launch_bounds__(256)
void attn_kernel(const float* __restrict__ mask,
                 const float* __restrict__ logit_scale,
                 const float* __restrict__ qkv_b)
{
    int bh = blockIdx.x;
    int b = bh / HEADS;
    int h = bh - b * HEADS;

    __shared__ float qs[64 * QKS];
    __shared__ float ks[64 * QKS];
    __shared__ float vs[64 * 33];
    __shared__ float sc[64 * SCS];

    int tid  = threadIdx.x;
    int warp = tid >> 5;
    int lane = tid & 31;
    int tr = tid >> 4;
    int tc = tid & 15;

    const float* qg = g_qkv + (long long)bh * (NTOK * HDIM);
    const float* kg = qg + QKV_STRIDE;
    const float* vg = kg + QKV_STRIDE;

    int cb = (tid & 7) * 4;
    float4 bv4 = *(const float4*)&qkv_b[2 * CDIM + h * HDIM + cb];

    for (int e = tid; e < 512; e += 256) {
        int r = e >> 3;
        int c = (e & 7) * 4;
        float4 q4 = ((const float4*)qg)[e];
        float4 k4 = ((const float4*)kg)[e];
        float4 v4 = ((const float4*)vg)[e];
        // stride-34 rows: float2 stores (8B-aligned since 34r+c is even)
        *(float2*)&qs[r * QKS + c]     = make_float2(q4.x, q4.y);
        *(float2*)&qs[r * QKS + c + 2] = make_float2(q4.z, q4.w);
        *(float2*)&ks[r * QKS + c]     = make_float2(k4.x, k4.y);
        *(float2*)&ks[r * QKS + c + 2] = make_float2(k4.z, k4.w);
        float* dv = &vs[r * 33 + c];
        dv[0] = v4.x + bv4.x; dv[1] = v4.y + bv4.y;
        dv[2] = v4.z + bv4.z; dv[3] = v4.w + bv4.w;
    }
    __syncthreads();

    float bq = qkv_b[h * HDIM + lane];
    float bk = qkv_b[CDIM + h * HDIM + lane];
    #pragma unroll
    for (int i = 0; i < 16; i++) {
        int r = warp * 16 + i;
        float* buf = (r < 64) ? &qs[r * QKS] : &ks[(r - 64) * QKS];
        float v = buf[lane] + ((r < 64) ? bq : bk);
        float ss = v * v;
        #pragma unroll
        for (int o = 16; o; o >>= 1) ss += __shfl_xor_sync(~0u, ss, o);
        buf[lane] = v / fmaxf(sqrtf(ss), 1e-12f);
    }
    __syncthreads();

    float scale = expf(fminf(logit_scale[h], 4.60517018598809f)); // ln(100)
    int w = b & (NWIN - 1);
    const float* mrow = mask + (long long)w * 4096;
    const float* brow = g_bias + h * 4096;

    // scores: 4x4 register tile, float2 along l
    {
        float acc[4][4];
        #pragma unroll
        for (int i = 0; i < 4; i++)
            #pragma unroll
            for (int j = 0; j < 4; j++) acc[i][j] = 0.f;
        #pragma unroll 4
        for (int l2 = 0; l2 < 16; l2++) {
            float2 qv[4], kv[4];
            #pragma unroll
            for (int i = 0; i < 4; i++)
                qv[i] = *(const float2*)&qs[(tr + 16 * i) * QKS + 2 * l2];
            #pragma unroll
            for (int j = 0; j < 4; j++)
                kv[j] = *(const float2*)&ks[(tc + 16 * j) * QKS + 2 * l2];
            #pragma unroll
            for (int i = 0; i < 4; i++)
                #pragma unroll
                for (int j = 0; j < 4; j++)
                    acc[i][j] += qv[i].x * kv[j].x + qv[i].y * kv[j].y;
        }
        #pragma unroll
        for (int i = 0; i < 4; i++) {
            int qi = tr + 16 * i;
            #pragma unroll
            for (int j = 0; j < 4; j++) {
                int kj = tc + 16 * j;
                int e = qi * 64 + kj;
                sc[qi * SCS + kj] = fmaf(acc[i][j], scale, brow[e] + mrow[e]);
            }
        }
    }
    __syncthreads();

    #pragma unroll
    for (int i = 0; i < 8; i++) {
        int qi = warp * 8 + i;
        float a = sc[qi * SCS + lane];
        float c = sc[qi * SCS + 32 + lane];
        float mx = fmaxf(a, c);
        #pragma unroll
        for (int o = 16; o; o >>= 1) mx = fmaxf(mx, __shfl_xor_sync(~0u, mx, o));
        a = __expf(a - mx);
        c = __expf(c - mx);
        float sm = a + c;
        #pragma unroll
        for (int o = 16; o; o >>= 1) sm += __shfl_xor_sync(~0u, sm, o);
        float inv = 1.f / sm;
        sc[qi * SCS + lane]      = a * inv;
        sc[qi * SCS + 32 + lane] = c * inv;
    }
    __syncthreads();

    // PV: 4x2 register tile, fp16 output
    {
        float acc[4][2];
        #pragma unroll
        for (int i = 0; i < 4; i++) { acc[i][0] = 0.f; acc[i][1] = 0.f; }
        #pragma unroll 4
        for (int kj = 0; kj < 64; kj++) {
            float pv[4], vv[2];
            #pragma unroll
            for (int i = 0; i < 4; i++) pv[i] = sc[(tr + 16 * i) * SCS + kj];
            vv[0] = vs[kj * 33 + tc];
            vv[1] = vs[kj * 33 + tc + 16];
            #pragma unroll
            for (int i = 0; i < 4; i++) {
                acc[i][0] += pv[i] * vv[0];
                acc[i][1] += pv[i] * vv[1];
            }
        }
        #pragma unroll
        for (int i = 0; i < 4; i++) {
            int qi = tr + 16 * i;
            long long rowo = ((long long)b * NTOK + qi) * CDIM + h * HDIM;
            g_att[rowo + tc]      = __float2half_rn(acc[i][0]);
            g_att[rowo + tc + 16] = __float2half_rn(acc[i][1]);
        }
    }
}

// ---------------------------------------------------------------------------
extern "C" void kernel_launch(void* const* d_in, const int* in_sizes, int n_in,
                              void* d_out, int out_size)
{
    const float* x           = (const float*)d_in[0];
    const float* mask        = (const float*)d_in[1];
    const float* qkv_w       = (const float*)d_in[2];
    const float* qkv_b       = (const float*)d_in[3];
    const float* proj_w      = (const float*)d_in[4];
    const float* proj_b      = (const float*)d_in[5];
    const float* logit_scale = (const float*)d_in[6];
    const float* cpb_w1      = (const float*)d_in[7];
    const float* cpb_b1      = (const float*)d_in[8];
    const float* cpb_w2      = (const float*)d_in[9];
    const float* rel_table   = (const float*)d_in[10];
    const int*   rel_index   = (const int*)d_in[11];
    float* out = (float*)d_out;

    static int attr_done = 0;
    if (!attr_done) {
        cudaFuncSetAttribute(hgemm_qkv,  cudaFuncAttributeMaxDynamicSharedMemorySize, HGEMM_SMEM_BYTES);
        cudaFuncSetAttribute(hgemm_proj, cudaFuncAttributeMaxDynamicSharedMemorySize, HGEMM_SMEM_BYTES);
        attr_done = 1;
    }

    // fp16 copies of x, qkv_w, proj_w (device symbol targets)
    __half* d_wh  = nullptr;
    __half* d_wph = nullptr;
    cudaGetSymbolAddress((void**)&d_wh,  g_wh);
    cudaGetSymbolAddress((void**)&d_wph, g_wph);

    convert_x_kernel<<<2048, 256>>>(x);
    convert_w_kernel<<<432, 256>>>(qkv_w, CDIM * QKV_N / 4, d_wh);
    convert_w_kernel<<<144, 256>>>(proj_w, CDIM * CDIM / 4, d_wph);

    cpb_tab_kernel<<<16, 256>>>(rel_table, cpb_w1, cpb_b1, cpb_w2);
    cpb_gather_kernel<<<192, 256>>>(rel_index);

    // qkv gemm: [262144,384] x [384,1152], fp16 in / fp32 accum
    {
        dim3 grid(QKV_N / 128, M1 / 128);
        hgemm_qkv<<<grid, 256, HGEMM_SMEM_BYTES>>>();
    }

    attn_kernel<<<BWIN * HEADS, 256>>>(mask, logit_scale, qkv_b);

    // proj gemm: [262144,384] x [384,384], fp16 in / fp32 accum
    {
        dim3 grid(CDIM / 128, M1 / 128);
        hgemm_proj<<<grid, 256, HGEMM_SMEM_BYTES>>>(proj_b, out);
    }
}